// round 2
// baseline (speedup 1.0000x reference)
#include <cuda_runtime.h>
#include <math.h>

// Problem constants: proj_z1/proj_z2 are (64, 64, 256) fp32 -> NS=4096 rows each,
// M=8192 total rows, D=256. loss = mean_i( lse_i - pos_i/T ).
#define M_TOT 8192
#define NS    4096
#define DDIM  256
#define INV_T 14.285714285714286f   // 1 / 0.07

// Scratch (allocation-free rule: __device__ globals)
__device__ float g_feat[M_TOT * DDIM];   // normalized features, 8 MB
__device__ float g_acc[M_TOT];           // sum_j!=i exp((sim-1)/T)
__device__ float g_pos[NS];              // dot(f1_j, f2_j)

// ---------------------------------------------------------------------------
// Kernel 1: clean + L2-normalize each row; also zero the accumulator.
// grid = M_TOT blocks, 256 threads (one element per thread).
// ---------------------------------------------------------------------------
__global__ __launch_bounds__(256) void normalize_kernel(
    const float* __restrict__ z1, const float* __restrict__ z2) {
    int row = blockIdx.x;
    int t = threadIdx.x;
    const float* src = (row < NS) ? (z1 + (size_t)row * DDIM)
                                  : (z2 + (size_t)(row - NS) * DDIM);
    float x = src[t];
    if (!isfinite(x)) x = 0.0f;
    float ss = x * x;
#pragma unroll
    for (int off = 16; off; off >>= 1)
        ss += __shfl_xor_sync(0xffffffffu, ss, off);
    __shared__ float wsum[8];
    __shared__ float s_inv;
    int lane = t & 31, w = t >> 5;
    if (lane == 0) wsum[w] = ss;
    __syncthreads();
    if (t == 0) {
        float tot = 0.0f;
#pragma unroll
        for (int i = 0; i < 8; i++) tot += wsum[i];
        s_inv = 1.0f / fmaxf(sqrtf(tot), 1e-12f);
        g_acc[row] = 0.0f;
    }
    __syncthreads();
    g_feat[(size_t)row * DDIM + t] = x * s_inv;
}

// ---------------------------------------------------------------------------
// Kernel 2: positive-pair dots pos[j] = dot(feat[j], feat[j+NS]).
// grid = NS blocks, 256 threads.
// ---------------------------------------------------------------------------
__global__ __launch_bounds__(256) void pos_kernel() {
    int j = blockIdx.x;
    int t = threadIdx.x;
    float p = g_feat[(size_t)j * DDIM + t] * g_feat[(size_t)(j + NS) * DDIM + t];
#pragma unroll
    for (int off = 16; off; off >>= 1)
        p += __shfl_xor_sync(0xffffffffu, p, off);
    __shared__ float wsum[8];
    int lane = t & 31, w = t >> 5;
    if (lane == 0) wsum[w] = p;
    __syncthreads();
    if (t == 0) {
        float tot = 0.0f;
#pragma unroll
        for (int i = 0; i < 8; i++) tot += wsum[i];
        g_pos[j] = tot;
    }
}

// ---------------------------------------------------------------------------
// Kernel 3: fused sim-tile GEMM + exp + row/col sums, upper triangle only.
// 64x64 output tile per block, 256 threads (16x16, 4x4 microtile), K-chunk 16.
// Fixed-shift softmax: exp((sim - 1)/T); diagonal elements masked to 0.
// Off-diagonal tiles feed both acc[rows of bi] (row sums) and acc[rows of bj]
// (column sums, via symmetry of sim).
// ---------------------------------------------------------------------------
__global__ __launch_bounds__(256) void sim_kernel() {
    int bi = blockIdx.y, bj = blockIdx.x;
    if (bj < bi) return;   // lower triangle: covered by symmetry

    __shared__ __align__(16) float As[16][68];   // [k][m], padded
    __shared__ __align__(16) float Bs[16][68];   // [k][n], padded
    __shared__ float colpart[16][65];

    int t  = threadIdx.x;
    int tx = t & 15, ty = t >> 4;
    int lr = t >> 2;            // 0..63 : row of tile this thread loads
    int lk = (t & 3) << 2;      // 0,4,8,12 : k-offset (float4)

    const float* Arow = g_feat + (size_t)(bi * 64 + lr) * DDIM;
    const float* Brow = g_feat + (size_t)(bj * 64 + lr) * DDIM;

    float c[4][4] = {};

    for (int kc = 0; kc < DDIM; kc += 16) {
        float4 av = *(const float4*)(Arow + kc + lk);
        float4 bv = *(const float4*)(Brow + kc + lk);
        __syncthreads();
        As[lk + 0][lr] = av.x; As[lk + 1][lr] = av.y;
        As[lk + 2][lr] = av.z; As[lk + 3][lr] = av.w;
        Bs[lk + 0][lr] = bv.x; Bs[lk + 1][lr] = bv.y;
        Bs[lk + 2][lr] = bv.z; Bs[lk + 3][lr] = bv.w;
        __syncthreads();
#pragma unroll
        for (int k = 0; k < 16; k++) {
            float4 a = *(const float4*)(&As[k][ty << 2]);
            float4 b = *(const float4*)(&Bs[k][tx << 2]);
            c[0][0] += a.x * b.x; c[0][1] += a.x * b.y;
            c[0][2] += a.x * b.z; c[0][3] += a.x * b.w;
            c[1][0] += a.y * b.x; c[1][1] += a.y * b.y;
            c[1][2] += a.y * b.z; c[1][3] += a.y * b.w;
            c[2][0] += a.z * b.x; c[2][1] += a.z * b.y;
            c[2][2] += a.z * b.z; c[2][3] += a.z * b.w;
            c[3][0] += a.w * b.x; c[3][1] += a.w * b.y;
            c[3][2] += a.w * b.z; c[3][3] += a.w * b.w;
        }
    }

    bool diag = (bi == bj);
    float rowsum[4] = {0.f, 0.f, 0.f, 0.f};
    float colsum[4] = {0.f, 0.f, 0.f, 0.f};
#pragma unroll
    for (int i = 0; i < 4; i++) {
#pragma unroll
        for (int j = 0; j < 4; j++) {
            float e = __expf((c[i][j] - 1.0f) * INV_T);
            if (diag && (ty * 4 + i == tx * 4 + j)) e = 0.0f;
            rowsum[i] += e;
            colsum[j] += e;
        }
    }

    // Row sums: butterfly over the 16 tx lanes (stays within 16-lane halves).
#pragma unroll
    for (int i = 0; i < 4; i++) {
#pragma unroll
        for (int off = 8; off; off >>= 1)
            rowsum[i] += __shfl_xor_sync(0xffffffffu, rowsum[i], off);
    }
    if (tx == 0) {
#pragma unroll
        for (int i = 0; i < 4; i++)
            atomicAdd(&g_acc[bi * 64 + ty * 4 + i], rowsum[i]);
    }

    // Column sums (only off-diagonal tiles; diagonal already fully row-summed).
    if (!diag) {
#pragma unroll
        for (int j = 0; j < 4; j++) colpart[ty][tx * 4 + j] = colsum[j];
        __syncthreads();
        if (t < 64) {
            float s = 0.0f;
#pragma unroll
            for (int y = 0; y < 16; y++) s += colpart[y][t];
            atomicAdd(&g_acc[bj * 64 + t], s);
        }
    }
}

// ---------------------------------------------------------------------------
// Kernel 4: loss = mean_i( 1/T + log(acc_i) - pos[i % NS] / T ).
// ---------------------------------------------------------------------------
__global__ __launch_bounds__(1024) void final_kernel(float* __restrict__ out) {
    int t = threadIdx.x;
    double s = 0.0;
    for (int i = t; i < M_TOT; i += 1024) {
        s += (double)INV_T + (double)logf(g_acc[i])
           - (double)g_pos[i & (NS - 1)] * (double)INV_T;
    }
#pragma unroll
    for (int off = 16; off; off >>= 1)
        s += __shfl_xor_sync(0xffffffffu, s, off);
    __shared__ double ws[32];
    int lane = t & 31, w = t >> 5;
    if (lane == 0) ws[w] = s;
    __syncthreads();
    if (t == 0) {
        double tot = 0.0;
#pragma unroll
        for (int i = 0; i < 32; i++) tot += ws[i];
        out[0] = (float)(tot / (double)M_TOT);
    }
}

// ---------------------------------------------------------------------------
extern "C" void kernel_launch(void* const* d_in, const int* in_sizes, int n_in,
                              void* d_out, int out_size) {
    (void)in_sizes; (void)n_in; (void)out_size;
    const float* z1 = (const float*)d_in[0];
    const float* z2 = (const float*)d_in[1];
    float* out = (float*)d_out;

    normalize_kernel<<<M_TOT, 256>>>(z1, z2);
    pos_kernel<<<NS, 256>>>();
    dim3 grid(128, 128);
    sim_kernel<<<grid, 256>>>();
    final_kernel<<<1, 1024>>>(out);
}

// round 4
// speedup vs baseline: 5.1953x; 5.1953x over previous
#include <cuda_runtime.h>
#include <cuda_bf16.h>
#include <math.h>
#include <cstdint>

#define M_TOT 8192
#define NS    4096
#define DDIM  256
#define INV_T 14.285714285714286f   // 1 / 0.07

#define ROW_STRIDE 528               // smem bytes per tile row (264 bf16, pad 8)
#define TILE_BYTES (128 * ROW_STRIDE)
#define SMEM_A 0
#define SMEM_B TILE_BYTES
#define SMEM_TOTAL (2 * TILE_BYTES)  // 135168 B

// Scratch (allocation-free rule: __device__ globals)
__device__ __align__(16) __nv_bfloat16 g_featb[M_TOT * DDIM];  // 4 MB
__device__ float g_acc[M_TOT];
__device__ float g_pos[NS];

// ---------------- helpers ----------------
__device__ __forceinline__ uint32_t smem_u32(const void* p) {
    uint32_t a;
    asm("{ .reg .u64 t; cvta.to.shared.u64 t, %1; cvt.u32.u64 %0, t; }" : "=r"(a) : "l"(p));
    return a;
}
#define CP16(dst, src) \
    asm volatile("cp.async.cg.shared.global [%0], [%1], 16;" :: "r"(dst), "l"(src))

#define LDSM4(r0, r1, r2, r3, addr) \
    asm volatile("ldmatrix.sync.aligned.m8n8.x4.shared.b16 {%0,%1,%2,%3}, [%4];" \
                 : "=r"(r0), "=r"(r1), "=r"(r2), "=r"(r3) : "r"(addr))

#define MMA16816(c0, c1, c2, c3, a0, a1, a2, a3, b0, b1) \
    asm volatile("mma.sync.aligned.m16n8k16.row.col.f32.bf16.bf16.f32 " \
                 "{%0,%1,%2,%3},{%4,%5,%6,%7},{%8,%9},{%0,%1,%2,%3};" \
                 : "+f"(c0), "+f"(c1), "+f"(c2), "+f"(c3) \
                 : "r"(a0), "r"(a1), "r"(a2), "r"(a3), "r"(b0), "r"(b1))

// ---------------------------------------------------------------------------
// Kernel 1: clean + L2-normalize rows -> bf16; zero accumulators + out.
// ---------------------------------------------------------------------------
__global__ __launch_bounds__(256) void normalize_kernel(
    const float* __restrict__ z1, const float* __restrict__ z2, float* __restrict__ out) {
    int row = blockIdx.x;
    int t = threadIdx.x;
    const float* src = (row < NS) ? (z1 + (size_t)row * DDIM)
                                  : (z2 + (size_t)(row - NS) * DDIM);
    float x = src[t];
    if (!isfinite(x)) x = 0.0f;
    float ss = x * x;
#pragma unroll
    for (int off = 16; off; off >>= 1)
        ss += __shfl_xor_sync(0xffffffffu, ss, off);
    __shared__ float wsum[8];
    __shared__ float s_inv;
    int lane = t & 31, w = t >> 5;
    if (lane == 0) wsum[w] = ss;
    __syncthreads();
    if (t == 0) {
        float tot = 0.0f;
#pragma unroll
        for (int i = 0; i < 8; i++) tot += wsum[i];
        s_inv = 1.0f / fmaxf(sqrtf(tot), 1e-12f);
        g_acc[row] = 0.0f;
        if (row == 0) out[0] = 0.0f;
    }
    __syncthreads();
    g_featb[(size_t)row * DDIM + t] = __float2bfloat16(x * s_inv);
}

// ---------------------------------------------------------------------------
// Kernel 2: positive-pair dots pos[j] = dot(feat[j], feat[j+NS])
// ---------------------------------------------------------------------------
__global__ __launch_bounds__(256) void pos_kernel() {
    int j = blockIdx.x;
    int t = threadIdx.x;
    float a = __bfloat162float(g_featb[(size_t)j * DDIM + t]);
    float b = __bfloat162float(g_featb[(size_t)(j + NS) * DDIM + t]);
    float p = a * b;
#pragma unroll
    for (int off = 16; off; off >>= 1)
        p += __shfl_xor_sync(0xffffffffu, p, off);
    __shared__ float wsum[8];
    int lane = t & 31, w = t >> 5;
    if (lane == 0) wsum[w] = p;
    __syncthreads();
    if (t == 0) {
        float tot = 0.0f;
#pragma unroll
        for (int i = 0; i < 8; i++) tot += wsum[i];
        g_pos[j] = tot;
    }
}

// ---------------------------------------------------------------------------
// Kernel 3: fused HMMA sim GEMM + exp + row/col sums, upper triangle.
// CTA tile 128x128, 8 warps in 4x2 (warp tile 32x64), K=256 in 4 pipelined
// cp.async chunks. exp((s-1)/T) fixed shift; diag masked; off-diag tiles add
// row sums (bi rows) and col sums (bj rows, symmetry).
// ---------------------------------------------------------------------------
struct Frag { float c[2][8][4]; };

__device__ __forceinline__ void compute_chunk(
    int kc, uint32_t aab, uint32_t bbb, Frag& f) {
#pragma unroll
    for (int ks = 0; ks < 4; ks++) {
        uint32_t kb = (uint32_t)((kc * 64 + ks * 16) * 2);
        uint32_t a0[4], a1[4];
        LDSM4(a0[0], a0[1], a0[2], a0[3], aab + kb);
        LDSM4(a1[0], a1[1], a1[2], a1[3], aab + 16 * ROW_STRIDE + kb);
#pragma unroll
        for (int jj = 0; jj < 4; jj++) {
            uint32_t b0, b1, b2, b3;
            LDSM4(b0, b1, b2, b3, bbb + jj * 16 * ROW_STRIDE + kb);
            // b0=(n0-7,k0-7) b1=(n8-15,k0-7) b2=(n0-7,k8-15) b3=(n8-15,k8-15)
            MMA16816(f.c[0][jj*2][0], f.c[0][jj*2][1], f.c[0][jj*2][2], f.c[0][jj*2][3],
                     a0[0], a0[1], a0[2], a0[3], b0, b2);
            MMA16816(f.c[0][jj*2+1][0], f.c[0][jj*2+1][1], f.c[0][jj*2+1][2], f.c[0][jj*2+1][3],
                     a0[0], a0[1], a0[2], a0[3], b1, b3);
            MMA16816(f.c[1][jj*2][0], f.c[1][jj*2][1], f.c[1][jj*2][2], f.c[1][jj*2][3],
                     a1[0], a1[1], a1[2], a1[3], b0, b2);
            MMA16816(f.c[1][jj*2+1][0], f.c[1][jj*2+1][1], f.c[1][jj*2+1][2], f.c[1][jj*2+1][3],
                     a1[0], a1[1], a1[2], a1[3], b1, b3);
        }
    }
}

__global__ __launch_bounds__(256, 1) void sim_kernel() {
    int bi = blockIdx.y, bj = blockIdx.x;
    if (bj < bi) return;     // lower triangle via symmetry

    extern __shared__ char smem[];
    uint32_t sb = smem_u32(smem);
    int t = threadIdx.x, lane = t & 31, wid = t >> 5;
    int warp_m = wid & 3, warp_n = wid >> 2;

    // Issue all tile loads: 4 commit groups, one per K-chunk of 64 cols.
    const char* gA = (const char*)(g_featb + (size_t)bi * 128 * DDIM);
    const char* gB = (const char*)(g_featb + (size_t)bj * 128 * DDIM);
#pragma unroll
    for (int kc = 0; kc < 4; kc++) {
#pragma unroll
        for (int o = 0; o < 4; o++) {
            int idx = t + o * 256;            // 0..1023
            int row = idx >> 3, seg = idx & 7;
            CP16(sb + SMEM_A + row * ROW_STRIDE + kc * 128 + seg * 16,
                 gA + row * 512 + kc * 128 + seg * 16);
        }
#pragma unroll
        for (int o = 0; o < 4; o++) {
            int idx = t + o * 256;
            int row = idx >> 3, seg = idx & 7;
            CP16(sb + SMEM_B + row * ROW_STRIDE + kc * 128 + seg * 16,
                 gB + row * 512 + kc * 128 + seg * 16);
        }
        asm volatile("cp.async.commit_group;" ::: "memory");
    }

    Frag f;
#pragma unroll
    for (int i = 0; i < 2; i++)
#pragma unroll
        for (int j = 0; j < 8; j++)
#pragma unroll
            for (int k = 0; k < 4; k++) f.c[i][j][k] = 0.0f;

    int lrow = lane & 15, khalf = lane >> 4;
    uint32_t aab = sb + SMEM_A + (warp_m * 32 + lrow) * ROW_STRIDE + khalf * 16;
    uint32_t bbb = sb + SMEM_B + (warp_n * 64 + lrow) * ROW_STRIDE + khalf * 16;

    asm volatile("cp.async.wait_group 3;" ::: "memory");
    __syncthreads();
    compute_chunk(0, aab, bbb, f);
    asm volatile("cp.async.wait_group 2;" ::: "memory");
    __syncthreads();
    compute_chunk(1, aab, bbb, f);
    asm volatile("cp.async.wait_group 1;" ::: "memory");
    __syncthreads();
    compute_chunk(2, aab, bbb, f);
    asm volatile("cp.async.wait_group 0;" ::: "memory");
    __syncthreads();
    compute_chunk(3, aab, bbb, f);

    // ---- Epilogue: exp + row sums + (off-diag) col sums ----
    bool diag = (bi == bj);
    int r0 = lane >> 2;          // 0..7
    int cq = (lane & 3) * 2;     // 0,2,4,6
    float rowsum[2][2] = {{0.f, 0.f}, {0.f, 0.f}};
    float colsum[8][2];
#pragma unroll
    for (int j = 0; j < 8; j++) { colsum[j][0] = 0.f; colsum[j][1] = 0.f; }

#pragma unroll
    for (int i = 0; i < 2; i++) {
        int grA = bi * 128 + warp_m * 32 + i * 16 + r0;
#pragma unroll
        for (int j = 0; j < 8; j++) {
            int gc = bj * 128 + warp_n * 64 + j * 8 + cq;
            float e0 = __expf(fmaf(f.c[i][j][0], INV_T, -INV_T));
            float e1 = __expf(fmaf(f.c[i][j][1], INV_T, -INV_T));
            float e2 = __expf(fmaf(f.c[i][j][2], INV_T, -INV_T));
            float e3 = __expf(fmaf(f.c[i][j][3], INV_T, -INV_T));
            if (diag) {
                if (grA == gc)         e0 = 0.0f;
                if (grA == gc + 1)     e1 = 0.0f;
                if (grA + 8 == gc)     e2 = 0.0f;
                if (grA + 8 == gc + 1) e3 = 0.0f;
            }
            rowsum[i][0] += e0 + e1;
            rowsum[i][1] += e2 + e3;
            colsum[j][0] += e0 + e2;
            colsum[j][1] += e1 + e3;
        }
    }

    // Row sums: reduce over the 4 lanes of each row quad (lane bits 0-1).
#pragma unroll
    for (int i = 0; i < 2; i++)
#pragma unroll
        for (int h = 0; h < 2; h++) {
            rowsum[i][h] += __shfl_xor_sync(0xffffffffu, rowsum[i][h], 1);
            rowsum[i][h] += __shfl_xor_sync(0xffffffffu, rowsum[i][h], 2);
        }
    if ((lane & 3) == 0) {
#pragma unroll
        for (int i = 0; i < 2; i++) {
            int gr = bi * 128 + warp_m * 32 + i * 16 + r0;
            atomicAdd(&g_acc[gr], rowsum[i][0]);
            atomicAdd(&g_acc[gr + 8], rowsum[i][1]);
        }
    }

    // Col sums (off-diag only): reduce over lanes differing in bits 2-4.
    if (!diag) {
#pragma unroll
        for (int j = 0; j < 8; j++)
#pragma unroll
            for (int h = 0; h < 2; h++) {
                colsum[j][h] += __shfl_xor_sync(0xffffffffu, colsum[j][h], 4);
                colsum[j][h] += __shfl_xor_sync(0xffffffffu, colsum[j][h], 8);
                colsum[j][h] += __shfl_xor_sync(0xffffffffu, colsum[j][h], 16);
            }
        if (lane < 4) {
#pragma unroll
            for (int j = 0; j < 8; j++) {
                int gc = bj * 128 + warp_n * 64 + j * 8 + lane * 2;
                atomicAdd(&g_acc[gc], colsum[j][0]);
                atomicAdd(&g_acc[gc + 1], colsum[j][1]);
            }
        }
    }
}

// ---------------------------------------------------------------------------
// Kernel 4: loss = mean_i( 1/T + log(acc_i) - pos[i % NS] / T ).
// ---------------------------------------------------------------------------
__global__ __launch_bounds__(1024) void final_kernel(float* __restrict__ out) {
    int t = threadIdx.x;
    int i = blockIdx.x * 1024 + t;
    float s = INV_T + __logf(g_acc[i]) - g_pos[i & (NS - 1)] * INV_T;
#pragma unroll
    for (int off = 16; off; off >>= 1)
        s += __shfl_xor_sync(0xffffffffu, s, off);
    __shared__ float ws[32];
    int lane = t & 31, w = t >> 5;
    if (lane == 0) ws[w] = s;
    __syncthreads();
    if (t == 0) {
        float tot = 0.0f;
#pragma unroll
        for (int k = 0; k < 32; k++) tot += ws[k];
        atomicAdd(out, tot * (1.0f / (float)M_TOT));
    }
}

// ---------------------------------------------------------------------------
extern "C" void kernel_launch(void* const* d_in, const int* in_sizes, int n_in,
                              void* d_out, int out_size) {
    (void)in_sizes; (void)n_in; (void)out_size;
    const float* z1 = (const float*)d_in[0];
    const float* z2 = (const float*)d_in[1];
    float* out = (float*)d_out;

    static int smem_set = 0;
    if (!smem_set) {
        cudaFuncSetAttribute(sim_kernel, cudaFuncAttributeMaxDynamicSharedMemorySize, SMEM_TOTAL);
        smem_set = 1;
    }

    normalize_kernel<<<M_TOT, 256>>>(z1, z2, out);
    pos_kernel<<<NS, 256>>>();
    dim3 grid(64, 64);
    sim_kernel<<<grid, 256, SMEM_TOTAL>>>();
    final_kernel<<<M_TOT / 1024, 1024>>>(out);
}

// round 5
// speedup vs baseline: 7.7410x; 1.4900x over previous
#include <cuda_runtime.h>
#include <cuda_bf16.h>
#include <math.h>
#include <cstdint>

#define M_TOT 8192
#define NS    4096
#define DDIM  256
#define INV_T 14.285714285714286f   // 1 / 0.07

// sim kernel: 128x128 tile, K in 4 chunks of 64 (128 B/row), 3-stage cp.async ring
#define CHUNK_BYTES   (128 * 128)            // one tile-chunk: 128 rows x 128 B
#define STAGE_BYTES   (2 * CHUNK_BYTES)      // A chunk + B chunk
#define NUM_STAGES    3
#define SMEM_TOTAL    (NUM_STAGES * STAGE_BYTES)   // 98304 B

// Scratch (allocation-free rule: __device__ globals)
__device__ __align__(16) __nv_bfloat16 g_featb[M_TOT * DDIM];  // 4 MB
__device__ float g_acc[M_TOT];
__device__ float g_pos[NS];

// ---------------- helpers ----------------
__device__ __forceinline__ uint32_t smem_u32(const void* p) {
    uint32_t a;
    asm("{ .reg .u64 t; cvta.to.shared.u64 t, %1; cvt.u32.u64 %0, t; }" : "=r"(a) : "l"(p));
    return a;
}
#define CP16(dst, src) \
    asm volatile("cp.async.cg.shared.global [%0], [%1], 16;" :: "r"(dst), "l"(src))
#define CP_COMMIT() asm volatile("cp.async.commit_group;" ::: "memory")
#define CP_WAIT(n)  asm volatile("cp.async.wait_group %0;" :: "n"(n) : "memory")

#define LDSM4(r0, r1, r2, r3, addr) \
    asm volatile("ldmatrix.sync.aligned.m8n8.x4.shared.b16 {%0,%1,%2,%3}, [%4];" \
                 : "=r"(r0), "=r"(r1), "=r"(r2), "=r"(r3) : "r"(addr))

#define MMA16816(c0, c1, c2, c3, a0, a1, a2, a3, b0, b1) \
    asm volatile("mma.sync.aligned.m16n8k16.row.col.f32.bf16.bf16.f32 " \
                 "{%0,%1,%2,%3},{%4,%5,%6,%7},{%8,%9},{%0,%1,%2,%3};" \
                 : "+f"(c0), "+f"(c1), "+f"(c2), "+f"(c3) \
                 : "r"(a0), "r"(a1), "r"(a2), "r"(a3), "r"(b0), "r"(b1))

// ---------------------------------------------------------------------------
// Kernel 1: clean + L2-normalize rows -> bf16. One warp per row (8 rows/block).
// Lane owns 8 consecutive floats (two float4 loads), writes 16 B of bf16.
// ---------------------------------------------------------------------------
__global__ __launch_bounds__(256) void normalize_kernel(
    const float* __restrict__ z1, const float* __restrict__ z2, float* __restrict__ out) {
    int w = threadIdx.x >> 5, lane = threadIdx.x & 31;
    int row = blockIdx.x * 8 + w;
    const float* src = (row < NS) ? (z1 + (size_t)row * DDIM)
                                  : (z2 + (size_t)(row - NS) * DDIM);
    float4 v0 = *(const float4*)(src + lane * 8);
    float4 v1 = *(const float4*)(src + lane * 8 + 4);
    float x[8] = {v0.x, v0.y, v0.z, v0.w, v1.x, v1.y, v1.z, v1.w};
    float ss = 0.0f;
#pragma unroll
    for (int i = 0; i < 8; i++) {
        if (!isfinite(x[i])) x[i] = 0.0f;
        ss = fmaf(x[i], x[i], ss);
    }
#pragma unroll
    for (int off = 16; off; off >>= 1)
        ss += __shfl_xor_sync(0xffffffffu, ss, off);
    float inv = 1.0f / fmaxf(sqrtf(ss), 1e-12f);
    __nv_bfloat162 o[4];
#pragma unroll
    for (int i = 0; i < 4; i++)
        o[i] = __floats2bfloat162_rn(x[2 * i] * inv, x[2 * i + 1] * inv);
    *(uint2*)(g_featb + (size_t)row * DDIM + lane * 8) = *(uint2*)&o[0];
    *(uint2*)(g_featb + (size_t)row * DDIM + lane * 8 + 4) = *(uint2*)&o[2];
    if (lane == 0) g_acc[row] = 0.0f;
    if (row == 0 && lane == 0) out[0] = 0.0f;
}

// ---------------------------------------------------------------------------
// Kernel 2: positive-pair dots. One warp per pair j: dot(feat[j], feat[j+NS]).
// ---------------------------------------------------------------------------
__global__ __launch_bounds__(256) void pos_kernel() {
    int w = threadIdx.x >> 5, lane = threadIdx.x & 31;
    int j = blockIdx.x * 8 + w;
    const __nv_bfloat16* ra = g_featb + (size_t)j * DDIM + lane * 8;
    const __nv_bfloat16* rb = g_featb + (size_t)(j + NS) * DDIM + lane * 8;
    uint2 ua = *(const uint2*)ra, ub = *(const uint2*)rb;
    uint2 ua2 = *(const uint2*)(ra + 4), ub2 = *(const uint2*)(rb + 4);
    const __nv_bfloat162* pa = (const __nv_bfloat162*)&ua;
    const __nv_bfloat162* pb = (const __nv_bfloat162*)&ub;
    const __nv_bfloat162* pa2 = (const __nv_bfloat162*)&ua2;
    const __nv_bfloat162* pb2 = (const __nv_bfloat162*)&ub2;
    float p = 0.0f;
#pragma unroll
    for (int i = 0; i < 2; i++) {
        float2 a = __bfloat1622float2(pa[i]), b = __bfloat1622float2(pb[i]);
        float2 a2 = __bfloat1622float2(pa2[i]), b2 = __bfloat1622float2(pb2[i]);
        p = fmaf(a.x, b.x, p); p = fmaf(a.y, b.y, p);
        p = fmaf(a2.x, b2.x, p); p = fmaf(a2.y, b2.y, p);
    }
#pragma unroll
    for (int off = 16; off; off >>= 1)
        p += __shfl_xor_sync(0xffffffffu, p, off);
    if (lane == 0) g_pos[j] = p;
}

// ---------------------------------------------------------------------------
// Kernel 3: fused HMMA sim GEMM + exp + row/col sums, upper triangle.
// 128x128 CTA tile, 8 warps (4x2, warp tile 32x64). K=256 streamed as 4 chunks
// of 64 cols; 3-stage cp.async ring (96 KB smem) -> 2 CTAs/SM. Chunk rows are
// 128 B with XOR-swizzled 16 B segments: conflict-free ldmatrix, no padding.
// ---------------------------------------------------------------------------
struct Frag { float c[2][8][4]; };

// load chunk kc of the tile starting at global row gr0 into stage st (A or B half)
__device__ __forceinline__ void load_chunk(uint32_t sb, int st, int half,
                                           const char* gbase, int kc, int t) {
    uint32_t dst0 = sb + (uint32_t)(st * STAGE_BYTES + half * CHUNK_BYTES);
#pragma unroll
    for (int o = 0; o < 4; o++) {
        int idx = t + o * 256;           // 0..1023
        int r = idx >> 3, seg = idx & 7;
        CP16(dst0 + r * 128 + ((seg ^ (r & 7)) << 4),
             gbase + r * 512 + kc * 128 + seg * 16);
    }
}

__device__ __forceinline__ void compute_chunk(
    uint32_t sb, int st, int warp_m, int warp_n, int lane, Frag& f) {
    int lrow = lane & 15, khalf = lane >> 4;
    uint32_t abase = sb + (uint32_t)(st * STAGE_BYTES);
    uint32_t bbase = abase + CHUNK_BYTES;
#pragma unroll
    for (int ks = 0; ks < 4; ks++) {
        int segk = 2 * ks + khalf;
        uint32_t a0[4], a1[4];
        {
            int r = warp_m * 32 + lrow;
            LDSM4(a0[0], a0[1], a0[2], a0[3], abase + r * 128 + ((segk ^ (r & 7)) << 4));
            r += 16;
            LDSM4(a1[0], a1[1], a1[2], a1[3], abase + r * 128 + ((segk ^ (r & 7)) << 4));
        }
#pragma unroll
        for (int jj = 0; jj < 4; jj++) {
            int r = warp_n * 64 + jj * 16 + lrow;
            uint32_t b0, b1, b2, b3;
            LDSM4(b0, b1, b2, b3, bbase + r * 128 + ((segk ^ (r & 7)) << 4));
            MMA16816(f.c[0][jj*2][0], f.c[0][jj*2][1], f.c[0][jj*2][2], f.c[0][jj*2][3],
                     a0[0], a0[1], a0[2], a0[3], b0, b2);
            MMA16816(f.c[0][jj*2+1][0], f.c[0][jj*2+1][1], f.c[0][jj*2+1][2], f.c[0][jj*2+1][3],
                     a0[0], a0[1], a0[2], a0[3], b1, b3);
            MMA16816(f.c[1][jj*2][0], f.c[1][jj*2][1], f.c[1][jj*2][2], f.c[1][jj*2][3],
                     a1[0], a1[1], a1[2], a1[3], b0, b2);
            MMA16816(f.c[1][jj*2+1][0], f.c[1][jj*2+1][1], f.c[1][jj*2+1][2], f.c[1][jj*2+1][3],
                     a1[0], a1[1], a1[2], a1[3], b1, b3);
        }
    }
}

__global__ __launch_bounds__(256, 2) void sim_kernel() {
    int bi = blockIdx.y, bj = blockIdx.x;
    if (bj < bi) return;     // lower triangle via symmetry

    extern __shared__ char smem[];
    uint32_t sb = smem_u32(smem);
    int t = threadIdx.x, lane = t & 31, wid = t >> 5;
    int warp_m = wid & 3, warp_n = wid >> 2;

    const char* gA = (const char*)(g_featb + (size_t)bi * 128 * DDIM);
    const char* gB = (const char*)(g_featb + (size_t)bj * 128 * DDIM);

    // 3-stage pipeline over 4 K-chunks
    load_chunk(sb, 0, 0, gA, 0, t); load_chunk(sb, 0, 1, gB, 0, t); CP_COMMIT();
    load_chunk(sb, 1, 0, gA, 1, t); load_chunk(sb, 1, 1, gB, 1, t); CP_COMMIT();
    load_chunk(sb, 2, 0, gA, 2, t); load_chunk(sb, 2, 1, gB, 2, t); CP_COMMIT();

    Frag f;
#pragma unroll
    for (int i = 0; i < 2; i++)
#pragma unroll
        for (int j = 0; j < 8; j++)
#pragma unroll
            for (int k = 0; k < 4; k++) f.c[i][j][k] = 0.0f;

    CP_WAIT(2); __syncthreads();
    compute_chunk(sb, 0, warp_m, warp_n, lane, f);
    __syncthreads();
    load_chunk(sb, 0, 0, gA, 3, t); load_chunk(sb, 0, 1, gB, 3, t); CP_COMMIT();
    CP_WAIT(2); __syncthreads();
    compute_chunk(sb, 1, warp_m, warp_n, lane, f);
    CP_WAIT(1); __syncthreads();
    compute_chunk(sb, 2, warp_m, warp_n, lane, f);
    CP_WAIT(0); __syncthreads();
    compute_chunk(sb, 0, warp_m, warp_n, lane, f);

    // ---- Epilogue: exp + row sums + (off-diag) col sums ----
    bool diag = (bi == bj);
    int r0 = lane >> 2;          // 0..7
    int cq = (lane & 3) * 2;     // 0,2,4,6
    float rowsum[2][2] = {{0.f, 0.f}, {0.f, 0.f}};
    float colsum[8][2];
#pragma unroll
    for (int j = 0; j < 8; j++) { colsum[j][0] = 0.f; colsum[j][1] = 0.f; }

#pragma unroll
    for (int i = 0; i < 2; i++) {
        int grA = bi * 128 + warp_m * 32 + i * 16 + r0;
#pragma unroll
        for (int j = 0; j < 8; j++) {
            int gc = bj * 128 + warp_n * 64 + j * 8 + cq;
            float e0 = __expf(fmaf(f.c[i][j][0], INV_T, -INV_T));
            float e1 = __expf(fmaf(f.c[i][j][1], INV_T, -INV_T));
            float e2 = __expf(fmaf(f.c[i][j][2], INV_T, -INV_T));
            float e3 = __expf(fmaf(f.c[i][j][3], INV_T, -INV_T));
            if (diag) {
                if (grA == gc)         e0 = 0.0f;
                if (grA == gc + 1)     e1 = 0.0f;
                if (grA + 8 == gc)     e2 = 0.0f;
                if (grA + 8 == gc + 1) e3 = 0.0f;
            }
            rowsum[i][0] += e0 + e1;
            rowsum[i][1] += e2 + e3;
            colsum[j][0] += e0 + e2;
            colsum[j][1] += e1 + e3;
        }
    }

#pragma unroll
    for (int i = 0; i < 2; i++)
#pragma unroll
        for (int h = 0; h < 2; h++) {
            rowsum[i][h] += __shfl_xor_sync(0xffffffffu, rowsum[i][h], 1);
            rowsum[i][h] += __shfl_xor_sync(0xffffffffu, rowsum[i][h], 2);
        }
    if ((lane & 3) == 0) {
#pragma unroll
        for (int i = 0; i < 2; i++) {
            int gr = bi * 128 + warp_m * 32 + i * 16 + r0;
            atomicAdd(&g_acc[gr], rowsum[i][0]);
            atomicAdd(&g_acc[gr + 8], rowsum[i][1]);
        }
    }

    if (!diag) {
#pragma unroll
        for (int j = 0; j < 8; j++)
#pragma unroll
            for (int h = 0; h < 2; h++) {
                colsum[j][h] += __shfl_xor_sync(0xffffffffu, colsum[j][h], 4);
                colsum[j][h] += __shfl_xor_sync(0xffffffffu, colsum[j][h], 8);
                colsum[j][h] += __shfl_xor_sync(0xffffffffu, colsum[j][h], 16);
            }
        if (lane < 4) {
#pragma unroll
            for (int j = 0; j < 8; j++) {
                int gc = bj * 128 + warp_n * 64 + j * 8 + lane * 2;
                atomicAdd(&g_acc[gc], colsum[j][0]);
                atomicAdd(&g_acc[gc + 1], colsum[j][1]);
            }
        }
    }
}

// ---------------------------------------------------------------------------
// Kernel 4: loss = mean_i( 1/T + log(acc_i) - pos[i % NS] / T ).
// ---------------------------------------------------------------------------
__global__ __launch_bounds__(256) void final_kernel(float* __restrict__ out) {
    int t = threadIdx.x;
    int i = blockIdx.x * 256 + t;
    float s = INV_T + __logf(g_acc[i]) - g_pos[i & (NS - 1)] * INV_T;
#pragma unroll
    for (int off = 16; off; off >>= 1)
        s += __shfl_xor_sync(0xffffffffu, s, off);
    __shared__ float ws[8];
    int lane = t & 31, w = t >> 5;
    if (lane == 0) ws[w] = s;
    __syncthreads();
    if (t == 0) {
        float tot = 0.0f;
#pragma unroll
        for (int k = 0; k < 8; k++) tot += ws[k];
        atomicAdd(out, tot * (1.0f / (float)M_TOT));
    }
}

// ---------------------------------------------------------------------------
extern "C" void kernel_launch(void* const* d_in, const int* in_sizes, int n_in,
                              void* d_out, int out_size) {
    (void)in_sizes; (void)n_in; (void)out_size;
    const float* z1 = (const float*)d_in[0];
    const float* z2 = (const float*)d_in[1];
    float* out = (float*)d_out;

    cudaFuncSetAttribute(sim_kernel, cudaFuncAttributeMaxDynamicSharedMemorySize, SMEM_TOTAL);

    normalize_kernel<<<M_TOT / 8, 256>>>(z1, z2, out);
    pos_kernel<<<NS / 8, 256>>>();
    dim3 grid(64, 64);
    sim_kernel<<<grid, 256, SMEM_TOTAL>>>();
    final_kernel<<<M_TOT / 256, 256>>>(out);
}